// round 1
// baseline (speedup 1.0000x reference)
#include <cuda_runtime.h>
#include <math.h>

#define H 1024
#define S 65536

// ---------------- scratch (no allocations allowed) ----------------
__device__ float  g_vpart[64 * H];      // 64 partial rows of v
__device__ float  g_v[H];               // v = W^T @ hidden
__device__ float  g_scores[S];          // raw scores
__device__ float2 g_bpart[8192];        // per-block (max, sumexp)
__device__ float2 g_MS;                 // global (max, sum)

// ---------------- kernel 1: partial v = W^T @ hidden ----------------
// block b handles i in [b*16, b*16+16); 256 threads cover all 1024 j via float4
__global__ void k_vpart(const float* __restrict__ hidden,
                        const float* __restrict__ W) {
    int t  = threadIdx.x;            // 0..255, one float4 of j each
    int i0 = blockIdx.x * 16;
    float4 acc = make_float4(0.f, 0.f, 0.f, 0.f);
#pragma unroll
    for (int ii = 0; ii < 16; ii++) {
        float h = __ldg(&hidden[i0 + ii]);
        float4 w = reinterpret_cast<const float4*>(W + (size_t)(i0 + ii) * H)[t];
        acc.x += h * w.x; acc.y += h * w.y; acc.z += h * w.z; acc.w += h * w.w;
    }
    reinterpret_cast<float4*>(g_vpart + (size_t)blockIdx.x * H)[t] = acc;
}

// ---------------- kernel 2: reduce 64 partials -> g_v ----------------
__global__ void k_vreduce() {
    int j = blockIdx.x * blockDim.x + threadIdx.x;   // 4 blocks x 256 = 1024
    float acc = 0.f;
#pragma unroll 8
    for (int p = 0; p < 64; p++) acc += g_vpart[p * H + j];
    g_v[j] = acc;
}

// ---------------- kernel 3: scores = enc @ v, + block softmax partials ----
// 8192 blocks x 256 threads; one warp per row (8 rows / block).
__global__ void __launch_bounds__(256) k_scores(const float* __restrict__ enc) {
    __shared__ float4 sv[256];
    __shared__ float  rowv[8];
    int t = threadIdx.x;
    sv[t] = reinterpret_cast<const float4*>(g_v)[t];
    __syncthreads();

    int warp = t >> 5, lane = t & 31;
    int row  = (blockIdx.x << 3) + warp;
    const float4* e = reinterpret_cast<const float4*>(enc + (size_t)row * H);

    float acc = 0.f;
#pragma unroll
    for (int k = 0; k < 8; k++) {
        float4 a = e[k * 32 + lane];
        float4 b = sv[k * 32 + lane];
        acc += a.x * b.x + a.y * b.y + a.z * b.z + a.w * b.w;
    }
#pragma unroll
    for (int o = 16; o; o >>= 1) acc += __shfl_xor_sync(0xffffffffu, acc, o);

    if (lane == 0) { g_scores[row] = acc; rowv[warp] = acc; }
    __syncthreads();

    if (t == 0) {
        float m = rowv[0];
#pragma unroll
        for (int i = 1; i < 8; i++) m = fmaxf(m, rowv[i]);
        float s = 0.f;
#pragma unroll
        for (int i = 0; i < 8; i++) s += expf(rowv[i] - m);
        g_bpart[blockIdx.x] = make_float2(m, s);
    }
}

// ---------------- kernel 4: merge 8192 (m,s) partials ----------------
__device__ __forceinline__ float2 ms_merge(float2 a, float2 b) {
    float m = fmaxf(a.x, b.x);
    return make_float2(m, a.y * expf(a.x - m) + b.y * expf(b.x - m));
}

__global__ void __launch_bounds__(1024) k_msreduce() {
    __shared__ float2 sm[1024];
    int t = threadIdx.x;
    float2 acc = make_float2(-INFINITY, 0.f);
#pragma unroll
    for (int k = 0; k < 8; k++) acc = ms_merge(acc, g_bpart[k * 1024 + t]);
    sm[t] = acc;
    __syncthreads();
    for (int off = 512; off; off >>= 1) {
        if (t < off) sm[t] = ms_merge(sm[t], sm[t + off]);
        __syncthreads();
    }
    if (t == 0) g_MS = sm[0];
}

// ---------------- kernel 5: normalize ----------------
__global__ void __launch_bounds__(256) k_norm(float* __restrict__ out) {
    int i = blockIdx.x * blockDim.x + threadIdx.x;   // 256 blocks x 256 = 65536
    float2 ms = g_MS;
    float inv = 1.f / ms.y;
    out[i] = expf(g_scores[i] - ms.x) * inv;
}

// ---------------- launch ----------------
extern "C" void kernel_launch(void* const* d_in, const int* in_sizes, int n_in,
                              void* d_out, int out_size) {
    const float* hidden = (const float*)d_in[0];   // [H]
    const float* enc    = (const float*)d_in[1];   // [S, H]
    const float* W      = (const float*)d_in[2];   // [H, H]
    // d_in[3] = b : dropped — softmax is shift-invariant to b.hidden
    float* out = (float*)d_out;                    // [S]

    k_vpart  <<<64,   256>>>(hidden, W);
    k_vreduce<<<4,    256>>>();
    k_scores <<<8192, 256>>>(enc);
    k_msreduce<<<1,  1024>>>();
    k_norm   <<<256,  256>>>(out);
}